// round 9
// baseline (speedup 1.0000x reference)
#include <cuda_runtime.h>
#include <math.h>

// EntropyBottleneck — SINGLE fused kernel.
//
// Structure exploited (verified per block at runtime):
//   * every m{i} constant-filled -> rank-1 layers
//   * every t{i} == 0            -> tanh gating vanishes
// => lower = alpha*x + beta_l, upper = alpha*x + beta_u per channel.
//
// Each block stages its channel's params in shared, verifies the structure
// (__syncthreads_and), folds {alpha, beta_l, beta_u}, then pure-streams its
// 8192-element slice. Cold full-MLP fallback path handles a failed channel
// (spilled by __launch_bounds__(256,6); never taken on this problem).

__device__ __forceinline__ float softplus_f(float v) {
    if (v > 20.0f) return v;
    if (v < -20.0f) return expf(v);
    return log1pf(expf(v));
}

__device__ __forceinline__ float sigmoid_fast(float x) {
    float e = __expf(-x);
    return __fdividef(1.0f, 1.0f + e);
}

#define EPB 8192   // 256 threads * 8 float4

__global__ __launch_bounds__(256, 6) void eb_fused(
    const float* __restrict__ in, float* __restrict__ out,
    const float* __restrict__ m0, const float* __restrict__ b0, const float* __restrict__ t0,
    const float* __restrict__ m1, const float* __restrict__ b1, const float* __restrict__ t1,
    const float* __restrict__ m2, const float* __restrict__ b2, const float* __restrict__ t2,
    const float* __restrict__ m3, const float* __restrict__ b3, const float* __restrict__ t3,
    const float* __restrict__ m4, const float* __restrict__ b4,
    int N, long long CN)
{
    const int c   = blockIdx.y;
    const int tid = threadIdx.x;

    __shared__ float sW0[3], sB0[3], sT0[3];
    __shared__ float sW[3][9], sBv[3][3], sT[3][3];
    __shared__ float sW4[3], sB4;
    __shared__ float sAlpha, sBl, sBu;

    // ---- Prologue: parallel param stage + structure check ------------------
    int ok = 1;
    if (tid < 3) {
        float v = __ldg(&m0[c * 3 + tid]);
        if (v != __ldg(&m0[c * 3])) ok = 0;
        sW0[tid] = softplus_f(v);
        sB0[tid] = __ldg(&b0[c * 3 + tid]);
        float tv = __ldg(&t0[c * 3 + tid]);
        if (tv != 0.0f) ok = 0;
        sT0[tid] = tanhf(tv);
    } else if (tid < 30) {
        int l = (tid - 3) / 9, j = (tid - 3) % 9;
        const float* m = (l == 0) ? m1 : (l == 1) ? m2 : m3;
        float v = __ldg(&m[c * 9 + j]);
        if (v != __ldg(&m[c * 9])) ok = 0;
        sW[l][j] = softplus_f(v);
    } else if (tid < 33) {
        int j = tid - 30;
        float v = __ldg(&m4[c * 3 + j]);
        if (v != __ldg(&m4[c * 3])) ok = 0;
        sW4[j] = softplus_f(v);
    } else if (tid < 42) {
        int l = (tid - 33) / 3, j = (tid - 33) % 3;
        const float* b = (l == 0) ? b1 : (l == 1) ? b2 : b3;
        const float* t = (l == 0) ? t1 : (l == 1) ? t2 : t3;
        sBv[l][j] = __ldg(&b[c * 3 + j]);
        float tv = __ldg(&t[c * 3 + j]);
        if (tv != 0.0f) ok = 0;
        sT[l][j] = tanhf(tv);
    } else if (tid == 42) {
        sB4 = __ldg(&b4[c]);
    }
    const int flag = __syncthreads_and(ok);

    if (tid == 0) {
        float alpha = sW0[0];
        alpha *= (sW[0][0] + sW[0][1] + sW[0][2]);
        alpha *= (sW[1][0] + sW[1][1] + sW[1][2]);
        alpha *= (sW[2][0] + sW[2][1] + sW[2][2]);
        alpha *= (sW4[0] + sW4[1] + sW4[2]);

        float y0 = sB0[0], y1 = sB0[1], y2 = sB0[2];
        #pragma unroll
        for (int l = 0; l < 3; l++) {
            float z0 = sW[l][0] * y0 + sW[l][1] * y1 + sW[l][2] * y2 + sBv[l][0];
            float z1 = sW[l][3] * y0 + sW[l][4] * y1 + sW[l][5] * y2 + sBv[l][1];
            float z2 = sW[l][6] * y0 + sW[l][7] * y1 + sW[l][8] * y2 + sBv[l][2];
            y0 = z0; y1 = z1; y2 = z2;
        }
        float beta = sW4[0] * y0 + sW4[1] * y1 + sW4[2] * y2 + sB4;
        float hb = 0.5f * alpha;
        sAlpha = alpha; sBl = beta - hb; sBu = beta + hb;
    }
    __syncthreads();

    const long long base = (long long)c * N;
    const int blk = blockIdx.x * EPB;
    const float* src = in + base;
    float* lik = out + base;
    float* low = out + CN + base;
    float* upp = out + 2 * CN + base;

    if (flag) {
        // ---- HOT: pure stream, 8 float4 per thread (paired-load ILP) ------
        const float alpha = sAlpha, bl = sBl, bu = sBu;
        if (blk + EPB <= N) {             // block-uniform interior predicate
            #pragma unroll
            for (int i = 0; i < 4; i++) {
                const int a0 = blk + i * 2048 + tid * 4;
                const int a1 = a0 + 1024;
                float4 x0 = __ldcs((const float4*)(src + a0));
                float4 x1 = __ldcs((const float4*)(src + a1));

                float4 l0, u0, k0;
                l0.x = fmaf(alpha, x0.x, bl); u0.x = fmaf(alpha, x0.x, bu);
                l0.y = fmaf(alpha, x0.y, bl); u0.y = fmaf(alpha, x0.y, bu);
                l0.z = fmaf(alpha, x0.z, bl); u0.z = fmaf(alpha, x0.z, bu);
                l0.w = fmaf(alpha, x0.w, bl); u0.w = fmaf(alpha, x0.w, bu);
                k0.x = sigmoid_fast(u0.x) - sigmoid_fast(l0.x);
                k0.y = sigmoid_fast(u0.y) - sigmoid_fast(l0.y);
                k0.z = sigmoid_fast(u0.z) - sigmoid_fast(l0.z);
                k0.w = sigmoid_fast(u0.w) - sigmoid_fast(l0.w);
                __stcs((float4*)(lik + a0), k0);
                __stcs((float4*)(low + a0), l0);
                __stcs((float4*)(upp + a0), u0);

                float4 l1, u1, k1;
                l1.x = fmaf(alpha, x1.x, bl); u1.x = fmaf(alpha, x1.x, bu);
                l1.y = fmaf(alpha, x1.y, bl); u1.y = fmaf(alpha, x1.y, bu);
                l1.z = fmaf(alpha, x1.z, bl); u1.z = fmaf(alpha, x1.z, bu);
                l1.w = fmaf(alpha, x1.w, bl); u1.w = fmaf(alpha, x1.w, bu);
                k1.x = sigmoid_fast(u1.x) - sigmoid_fast(l1.x);
                k1.y = sigmoid_fast(u1.y) - sigmoid_fast(l1.y);
                k1.z = sigmoid_fast(u1.z) - sigmoid_fast(l1.z);
                k1.w = sigmoid_fast(u1.w) - sigmoid_fast(l1.w);
                __stcs((float4*)(lik + a1), k1);
                __stcs((float4*)(low + a1), l1);
                __stcs((float4*)(upp + a1), u1);
            }
        } else {
            for (int i = 0; i < 8; i++) {
                int s = blk + i * 1024 + tid * 4;
                int lim = min(s + 4, N);
                for (int q = s; q < lim; q++) {
                    float x = src[q];
                    float l = fmaf(alpha, x, bl);
                    float u = fmaf(alpha, x, bu);
                    lik[q] = sigmoid_fast(u) - sigmoid_fast(l);
                    low[q] = l;
                    upp[q] = u;
                }
            }
        }
    } else {
        // ---- COLD safety net: full MLP for this block's slice -------------
        // (spilled under launch_bounds; never taken on this problem's inputs)
        const int end = min(blk + EPB, N);
        for (int e = blk + tid; e < end; e += 256) {
            float x = src[e];
            float r2[2];
            #pragma unroll
            for (int s = 0; s < 2; s++) {
                float xi = x + (s ? 0.5f : -0.5f);
                float y0 = fmaf(sW0[0], xi, sB0[0]);
                float y1 = fmaf(sW0[1], xi, sB0[1]);
                float y2 = fmaf(sW0[2], xi, sB0[2]);
                y0 = fmaf(sT0[0], tanhf(y0), y0);
                y1 = fmaf(sT0[1], tanhf(y1), y1);
                y2 = fmaf(sT0[2], tanhf(y2), y2);
                #pragma unroll
                for (int l = 0; l < 3; l++) {
                    float z0 = sW[l][0] * y0 + sW[l][1] * y1 + sW[l][2] * y2 + sBv[l][0];
                    float z1 = sW[l][3] * y0 + sW[l][4] * y1 + sW[l][5] * y2 + sBv[l][1];
                    float z2 = sW[l][6] * y0 + sW[l][7] * y1 + sW[l][8] * y2 + sBv[l][2];
                    y0 = fmaf(sT[l][0], tanhf(z0), z0);
                    y1 = fmaf(sT[l][1], tanhf(z1), z1);
                    y2 = fmaf(sT[l][2], tanhf(z2), z2);
                }
                r2[s] = sW4[0] * y0 + sW4[1] * y1 + sW4[2] * y2 + sB4;
            }
            lik[e] = 1.0f / (1.0f + expf(-r2[1])) - 1.0f / (1.0f + expf(-r2[0]));
            low[e] = r2[0];
            upp[e] = r2[1];
        }
    }
}

// ---------------------------------------------------------------------------
// Host launcher — single kernel launch.
// ---------------------------------------------------------------------------
extern "C" void kernel_launch(void* const* d_in, const int* in_sizes, int n_in,
                              void* d_out, int out_size)
{
    // Input-order detection.
    // Order A (dict order): inputs, m0,b0,t0, m1,b1,t1, m2,b2,t2, m3,b3,t3, m4,b4
    // Order B (signature):  inputs, m0..m4, b0..b4, t0..t3
    int im[5], ib[5], it[4];
    if (n_in >= 15 && in_sizes[2] == in_sizes[1]) {
        im[0] = 1;  ib[0] = 2;  it[0] = 3;
        im[1] = 4;  ib[1] = 5;  it[1] = 6;
        im[2] = 7;  ib[2] = 8;  it[2] = 9;
        im[3] = 10; ib[3] = 11; it[3] = 12;
        im[4] = 13; ib[4] = 14;
    } else {
        im[0] = 1; im[1] = 2; im[2] = 3; im[3] = 4; im[4] = 5;
        ib[0] = 6; ib[1] = 7; ib[2] = 8; ib[3] = 9; ib[4] = 10;
        it[0] = 11; it[1] = 12; it[2] = 13; it[3] = 14;
    }

    const float* in = (const float*)d_in[0];
    float* out = (float*)d_out;

    int C = in_sizes[ib[4]];          // b4 is (C,1,1)
    if (C <= 0) C = 192;
    int N = in_sizes[0] / C;
    long long CN = (long long)C * N;

    dim3 grid((N + EPB - 1) / EPB, C);
    eb_fused<<<grid, 256>>>(
        in, out,
        (const float*)d_in[im[0]], (const float*)d_in[ib[0]], (const float*)d_in[it[0]],
        (const float*)d_in[im[1]], (const float*)d_in[ib[1]], (const float*)d_in[it[1]],
        (const float*)d_in[im[2]], (const float*)d_in[ib[2]], (const float*)d_in[it[2]],
        (const float*)d_in[im[3]], (const float*)d_in[ib[3]], (const float*)d_in[it[3]],
        (const float*)d_in[im[4]], (const float*)d_in[ib[4]],
        N, CN);
}

// round 10
// speedup vs baseline: 1.0062x; 1.0062x over previous
#include <cuda_runtime.h>
#include <math.h>

// EntropyBottleneck — single fused kernel, prologue hidden under L2 prefetch.
//
// Structure exploited (verified per block at runtime):
//   * every m{i} constant-filled -> rank-1 layers
//   * every t{i} == 0            -> tanh gating vanishes
// => lower = alpha*x + beta_l, upper = alpha*x + beta_u per channel.
//
// Block flow:
//   1. ALL threads issue prefetch.global.L2 for their first input pair
//      (params-independent -> overlaps the prologue below).
//   2. Threads <43 stage params in shared, verify structure, softplus/tanh.
//   3. __syncthreads_and -> flag; thread 0 folds {alpha, beta_l, beta_u}.
//   4. Stream 8192 elems/block: 4x paired float4 loads, 2 FMA + 2 fast
//      sigmoids per elem, 3 float4 streaming stores.
// Cold full-MLP fallback (spilled via launch_bounds, never taken here).

__device__ __forceinline__ float softplus_f(float v) {
    if (v > 20.0f) return v;
    if (v < -20.0f) return expf(v);
    return log1pf(expf(v));
}

__device__ __forceinline__ float sigmoid_fast(float x) {
    float e = __expf(-x);
    return __fdividef(1.0f, 1.0f + e);
}

#define EPB 8192   // 256 threads * 8 float4

__global__ __launch_bounds__(256, 6) void eb_fused(
    const float* __restrict__ in, float* __restrict__ out,
    const float* __restrict__ m0, const float* __restrict__ b0, const float* __restrict__ t0,
    const float* __restrict__ m1, const float* __restrict__ b1, const float* __restrict__ t1,
    const float* __restrict__ m2, const float* __restrict__ b2, const float* __restrict__ t2,
    const float* __restrict__ m3, const float* __restrict__ b3, const float* __restrict__ t3,
    const float* __restrict__ m4, const float* __restrict__ b4,
    int N, long long CN)
{
    const int c   = blockIdx.y;
    const int tid = threadIdx.x;

    const long long base = (long long)c * N;
    const int blk = blockIdx.x * EPB;
    const float* src = in + base;

    // ---- Step 1: prefetch first input pair BEFORE any param work -----------
    {
        const float* p0 = src + blk + tid * 4;
        asm volatile("prefetch.global.L2 [%0];" :: "l"(p0));
        asm volatile("prefetch.global.L2 [%0];" :: "l"(p0 + 1024));
    }

    __shared__ float sW0[3], sB0[3], sT0[3];
    __shared__ float sW[3][9], sBv[3][3], sT[3][3];
    __shared__ float sW4[3], sB4;
    __shared__ float sAlpha, sBl, sBu;

    // ---- Step 2: parallel param stage + structure check --------------------
    int ok = 1;
    if (tid < 3) {
        float v = __ldg(&m0[c * 3 + tid]);
        if (v != __ldg(&m0[c * 3])) ok = 0;
        sW0[tid] = softplus_f(v);
        sB0[tid] = __ldg(&b0[c * 3 + tid]);
        float tv = __ldg(&t0[c * 3 + tid]);
        if (tv != 0.0f) ok = 0;
        sT0[tid] = tanhf(tv);
    } else if (tid < 30) {
        int l = (tid - 3) / 9, j = (tid - 3) % 9;
        const float* m = (l == 0) ? m1 : (l == 1) ? m2 : m3;
        float v = __ldg(&m[c * 9 + j]);
        if (v != __ldg(&m[c * 9])) ok = 0;
        sW[l][j] = softplus_f(v);
    } else if (tid < 33) {
        int j = tid - 30;
        float v = __ldg(&m4[c * 3 + j]);
        if (v != __ldg(&m4[c * 3])) ok = 0;
        sW4[j] = softplus_f(v);
    } else if (tid < 42) {
        int l = (tid - 33) / 3, j = (tid - 33) % 3;
        const float* b = (l == 0) ? b1 : (l == 1) ? b2 : b3;
        const float* t = (l == 0) ? t1 : (l == 1) ? t2 : t3;
        sBv[l][j] = __ldg(&b[c * 3 + j]);
        float tv = __ldg(&t[c * 3 + j]);
        if (tv != 0.0f) ok = 0;
        sT[l][j] = tanhf(tv);
    } else if (tid == 42) {
        sB4 = __ldg(&b4[c]);
    }
    const int flag = __syncthreads_and(ok);

    // ---- Step 3: thread 0 folds alpha/beta ---------------------------------
    if (tid == 0) {
        float alpha = sW0[0];
        alpha *= (sW[0][0] + sW[0][1] + sW[0][2]);
        alpha *= (sW[1][0] + sW[1][1] + sW[1][2]);
        alpha *= (sW[2][0] + sW[2][1] + sW[2][2]);
        alpha *= (sW4[0] + sW4[1] + sW4[2]);

        float y0 = sB0[0], y1 = sB0[1], y2 = sB0[2];
        #pragma unroll
        for (int l = 0; l < 3; l++) {
            float z0 = sW[l][0] * y0 + sW[l][1] * y1 + sW[l][2] * y2 + sBv[l][0];
            float z1 = sW[l][3] * y0 + sW[l][4] * y1 + sW[l][5] * y2 + sBv[l][1];
            float z2 = sW[l][6] * y0 + sW[l][7] * y1 + sW[l][8] * y2 + sBv[l][2];
            y0 = z0; y1 = z1; y2 = z2;
        }
        float beta = sW4[0] * y0 + sW4[1] * y1 + sW4[2] * y2 + sB4;
        float hb = 0.5f * alpha;
        sAlpha = alpha; sBl = beta - hb; sBu = beta + hb;
    }
    __syncthreads();

    float* lik = out + base;
    float* low = out + CN + base;
    float* upp = out + 2 * CN + base;

    if (flag) {
        // ---- Step 4 HOT: pure stream, 8 float4/thread (paired-load ILP) ---
        const float alpha = sAlpha, bl = sBl, bu = sBu;
        if (blk + EPB <= N) {             // block-uniform interior predicate
            #pragma unroll
            for (int i = 0; i < 4; i++) {
                const int a0 = blk + i * 2048 + tid * 4;
                const int a1 = a0 + 1024;
                float4 x0 = __ldcs((const float4*)(src + a0));
                float4 x1 = __ldcs((const float4*)(src + a1));

                float4 l0, u0, k0;
                l0.x = fmaf(alpha, x0.x, bl); u0.x = fmaf(alpha, x0.x, bu);
                l0.y = fmaf(alpha, x0.y, bl); u0.y = fmaf(alpha, x0.y, bu);
                l0.z = fmaf(alpha, x0.z, bl); u0.z = fmaf(alpha, x0.z, bu);
                l0.w = fmaf(alpha, x0.w, bl); u0.w = fmaf(alpha, x0.w, bu);
                k0.x = sigmoid_fast(u0.x) - sigmoid_fast(l0.x);
                k0.y = sigmoid_fast(u0.y) - sigmoid_fast(l0.y);
                k0.z = sigmoid_fast(u0.z) - sigmoid_fast(l0.z);
                k0.w = sigmoid_fast(u0.w) - sigmoid_fast(l0.w);
                __stcs((float4*)(lik + a0), k0);
                __stcs((float4*)(low + a0), l0);
                __stcs((float4*)(upp + a0), u0);

                float4 l1, u1, k1;
                l1.x = fmaf(alpha, x1.x, bl); u1.x = fmaf(alpha, x1.x, bu);
                l1.y = fmaf(alpha, x1.y, bl); u1.y = fmaf(alpha, x1.y, bu);
                l1.z = fmaf(alpha, x1.z, bl); u1.z = fmaf(alpha, x1.z, bu);
                l1.w = fmaf(alpha, x1.w, bl); u1.w = fmaf(alpha, x1.w, bu);
                k1.x = sigmoid_fast(u1.x) - sigmoid_fast(l1.x);
                k1.y = sigmoid_fast(u1.y) - sigmoid_fast(l1.y);
                k1.z = sigmoid_fast(u1.z) - sigmoid_fast(l1.z);
                k1.w = sigmoid_fast(u1.w) - sigmoid_fast(l1.w);
                __stcs((float4*)(lik + a1), k1);
                __stcs((float4*)(low + a1), l1);
                __stcs((float4*)(upp + a1), u1);
            }
        } else {
            for (int i = 0; i < 8; i++) {
                int s = blk + i * 1024 + tid * 4;
                int lim = min(s + 4, N);
                for (int q = s; q < lim; q++) {
                    float x = src[q];
                    float l = fmaf(alpha, x, bl);
                    float u = fmaf(alpha, x, bu);
                    lik[q] = sigmoid_fast(u) - sigmoid_fast(l);
                    low[q] = l;
                    upp[q] = u;
                }
            }
        }
    } else {
        // ---- COLD safety net: full MLP for this block's slice -------------
        const int end = min(blk + EPB, N);
        for (int e = blk + tid; e < end; e += 256) {
            float x = src[e];
            float r2[2];
            #pragma unroll
            for (int s = 0; s < 2; s++) {
                float xi = x + (s ? 0.5f : -0.5f);
                float y0 = fmaf(sW0[0], xi, sB0[0]);
                float y1 = fmaf(sW0[1], xi, sB0[1]);
                float y2 = fmaf(sW0[2], xi, sB0[2]);
                y0 = fmaf(sT0[0], tanhf(y0), y0);
                y1 = fmaf(sT0[1], tanhf(y1), y1);
                y2 = fmaf(sT0[2], tanhf(y2), y2);
                #pragma unroll
                for (int l = 0; l < 3; l++) {
                    float z0 = sW[l][0] * y0 + sW[l][1] * y1 + sW[l][2] * y2 + sBv[l][0];
                    float z1 = sW[l][3] * y0 + sW[l][4] * y1 + sW[l][5] * y2 + sBv[l][1];
                    float z2 = sW[l][6] * y0 + sW[l][7] * y1 + sW[l][8] * y2 + sBv[l][2];
                    y0 = fmaf(sT[l][0], tanhf(z0), z0);
                    y1 = fmaf(sT[l][1], tanhf(z1), z1);
                    y2 = fmaf(sT[l][2], tanhf(z2), z2);
                }
                r2[s] = sW4[0] * y0 + sW4[1] * y1 + sW4[2] * y2 + sB4;
            }
            lik[e] = 1.0f / (1.0f + expf(-r2[1])) - 1.0f / (1.0f + expf(-r2[0]));
            low[e] = r2[0];
            upp[e] = r2[1];
        }
    }
}

// ---------------------------------------------------------------------------
// Host launcher — single kernel launch.
// ---------------------------------------------------------------------------
extern "C" void kernel_launch(void* const* d_in, const int* in_sizes, int n_in,
                              void* d_out, int out_size)
{
    // Input-order detection.
    // Order A (dict order): inputs, m0,b0,t0, m1,b1,t1, m2,b2,t2, m3,b3,t3, m4,b4
    // Order B (signature):  inputs, m0..m4, b0..b4, t0..t3
    int im[5], ib[5], it[4];
    if (n_in >= 15 && in_sizes[2] == in_sizes[1]) {
        im[0] = 1;  ib[0] = 2;  it[0] = 3;
        im[1] = 4;  ib[1] = 5;  it[1] = 6;
        im[2] = 7;  ib[2] = 8;  it[2] = 9;
        im[3] = 10; ib[3] = 11; it[3] = 12;
        im[4] = 13; ib[4] = 14;
    } else {
        im[0] = 1; im[1] = 2; im[2] = 3; im[3] = 4; im[4] = 5;
        ib[0] = 6; ib[1] = 7; ib[2] = 8; ib[3] = 9; ib[4] = 10;
        it[0] = 11; it[1] = 12; it[2] = 13; it[3] = 14;
    }

    const float* in = (const float*)d_in[0];
    float* out = (float*)d_out;

    int C = in_sizes[ib[4]];          // b4 is (C,1,1)
    if (C <= 0) C = 192;
    int N = in_sizes[0] / C;
    long long CN = (long long)C * N;

    dim3 grid((N + EPB - 1) / EPB, C);
    eb_fused<<<grid, 256>>>(
        in, out,
        (const float*)d_in[im[0]], (const float*)d_in[ib[0]], (const float*)d_in[it[0]],
        (const float*)d_in[im[1]], (const float*)d_in[ib[1]], (const float*)d_in[it[1]],
        (const float*)d_in[im[2]], (const float*)d_in[ib[2]], (const float*)d_in[it[2]],
        (const float*)d_in[im[3]], (const float*)d_in[ib[3]], (const float*)d_in[it[3]],
        (const float*)d_in[im[4]], (const float*)d_in[ib[4]],
        N, CN);
}

// round 11
// speedup vs baseline: 1.0407x; 1.0344x over previous
#include <cuda_runtime.h>
#include <math.h>

// EntropyBottleneck — single kernel, intra-kernel producer/consumer params.
//
// Structure exploited (verified at runtime per channel):
//   * every m{i} constant-filled -> rank-1 layers
//   * every t{i} == 0            -> tanh gating vanishes
// => lower = alpha*x + beta_l, upper = alpha*x + beta_u per channel.
//
// Block (0,c) produces channel c's params (parallel fold, publish, fence,
// flag). All other blocks of channel c poll the flag (overlapped with their
// own input prefetch), broadcast {alpha,beta_l,beta_u} via shared, stream.
// flag==2 => full-MLP fallback from published params (never taken here).

__device__ float4 g_abv[256];      // {alpha, beta_l, beta_u, -}
__device__ int    g_flag[256];     // 0 = not ready, 1 = affine, 2 = fallback
__device__ float  g_pf[256][64];   // full transformed params (fallback only)

// Flat param layout (shared + g_pf):
//  [0..2] W0 [3..5] B0 [6..8] T0
//  layer l in {0,1,2}: base=9+l*15 -> W[0..8], B[9..11], T[12..14]
//  [54..56] W4  [57] B4
#define NPARAM 58

__device__ __forceinline__ float softplus_f(float v) {
    if (v > 20.0f) return v;
    if (v < -20.0f) return expf(v);
    return log1pf(expf(v));
}

__device__ __forceinline__ float sigmoid_fast(float x) {
    float e = __expf(-x);
    return __fdividef(1.0f, 1.0f + e);
}

#define EPB 4096   // 256 threads * 4 float4

__global__ __launch_bounds__(256, 6) void eb_kernel(
    const float* __restrict__ in, float* __restrict__ out,
    const float* __restrict__ m0, const float* __restrict__ b0, const float* __restrict__ t0,
    const float* __restrict__ m1, const float* __restrict__ b1, const float* __restrict__ t1,
    const float* __restrict__ m2, const float* __restrict__ b2, const float* __restrict__ t2,
    const float* __restrict__ m3, const float* __restrict__ b3, const float* __restrict__ t3,
    const float* __restrict__ m4, const float* __restrict__ b4,
    int N, long long CN)
{
    const int c   = blockIdx.y;
    const int tid = threadIdx.x;

    const long long base = (long long)c * N;
    const int blk = blockIdx.x * EPB;
    const float* src = in + base;

    // Prefetch this block's first input pair (overlaps producer fold / spin).
    {
        const float* p0 = src + blk + tid * 4;
        asm volatile("prefetch.global.L2 [%0];" :: "l"(p0));
        asm volatile("prefetch.global.L2 [%0];" :: "l"(p0 + 1024));
    }

    __shared__ float sP[NPARAM];
    __shared__ float sAlpha, sBl, sBu;
    __shared__ int   sState;

    if (blockIdx.x == 0) {
        // ================= PRODUCER (one block per channel) =================
        int ok = 1;
        if (tid < 3) {
            float v = __ldg(&m0[c * 3 + tid]);
            if (v != __ldg(&m0[c * 3])) ok = 0;
            sP[0 + tid] = softplus_f(v);
            sP[3 + tid] = __ldg(&b0[c * 3 + tid]);
            float tv = __ldg(&t0[c * 3 + tid]);
            if (tv != 0.0f) ok = 0;
            sP[6 + tid] = tanhf(tv);
        } else if (tid < 30) {
            int l = (tid - 3) / 9, j = (tid - 3) % 9;
            const float* m = (l == 0) ? m1 : (l == 1) ? m2 : m3;
            float v = __ldg(&m[c * 9 + j]);
            if (v != __ldg(&m[c * 9])) ok = 0;
            sP[9 + l * 15 + j] = softplus_f(v);
        } else if (tid < 33) {
            int j = tid - 30;
            float v = __ldg(&m4[c * 3 + j]);
            if (v != __ldg(&m4[c * 3])) ok = 0;
            sP[54 + j] = softplus_f(v);
        } else if (tid < 42) {
            int l = (tid - 33) / 3, j = (tid - 33) % 3;
            const float* b = (l == 0) ? b1 : (l == 1) ? b2 : b3;
            const float* t = (l == 0) ? t1 : (l == 1) ? t2 : t3;
            sP[9 + l * 15 + 9 + j] = __ldg(&b[c * 3 + j]);
            float tv = __ldg(&t[c * 3 + j]);
            if (tv != 0.0f) ok = 0;
            sP[9 + l * 15 + 12 + j] = tanhf(tv);
        } else if (tid == 42) {
            sP[57] = __ldg(&b4[c]);
        }
        const int flag = __syncthreads_and(ok);

        if (!flag && tid < NPARAM) g_pf[c][tid] = sP[tid];   // fallback params

        if (tid == 0) {
            float alpha = sP[0];
            alpha *= (sP[9]  + sP[10] + sP[11]);
            alpha *= (sP[24] + sP[25] + sP[26]);
            alpha *= (sP[39] + sP[40] + sP[41]);
            alpha *= (sP[54] + sP[55] + sP[56]);

            float y0 = sP[3], y1 = sP[4], y2 = sP[5];
            #pragma unroll
            for (int l = 0; l < 3; l++) {
                const float* W = sP + 9 + l * 15;
                const float* B = W + 9;
                float z0 = W[0] * y0 + W[1] * y1 + W[2] * y2 + B[0];
                float z1 = W[3] * y0 + W[4] * y1 + W[5] * y2 + B[1];
                float z2 = W[6] * y0 + W[7] * y1 + W[8] * y2 + B[2];
                y0 = z0; y1 = z1; y2 = z2;
            }
            float beta = sP[54] * y0 + sP[55] * y1 + sP[56] * y2 + sP[57];
            float hb = 0.5f * alpha;
            sAlpha = alpha; sBl = beta - hb; sBu = beta + hb;
            sState = flag ? 1 : 2;
            g_abv[c] = make_float4(alpha, beta - hb, beta + hb, 0.0f);
            __threadfence();                          // publish before flag
            atomicExch(&g_flag[c], flag ? 1 : 2);     // release
        }
        __syncthreads();
    } else {
        // ================= CONSUMER =========================================
        if (tid == 0) {
            int f = atomicOr(&g_flag[c], 0);
            while (f == 0) { __nanosleep(64); f = atomicOr(&g_flag[c], 0); }
            __threadfence();                          // acquire
            sState = f;
            float4 v;
            v.x = __ldcg(&g_abv[c].x);
            v.y = __ldcg(&g_abv[c].y);
            v.z = __ldcg(&g_abv[c].z);
            sAlpha = v.x; sBl = v.y; sBu = v.z;
        }
        __syncthreads();
        if (sState == 2 && tid < NPARAM) sP[tid] = __ldcg(&g_pf[c][tid]);
        if (sState == 2) __syncthreads();
    }

    float* lik = out + base;
    float* low = out + CN + base;
    float* upp = out + 2 * CN + base;

    if (sState == 1) {
        // ---- HOT stream: 4 float4/thread, paired-load ILP ------------------
        const float alpha = sAlpha, bl = sBl, bu = sBu;
        if (blk + EPB <= N) {             // block-uniform interior predicate
            #pragma unroll
            for (int i = 0; i < 2; i++) {
                const int a0 = blk + i * 2048 + tid * 4;
                const int a1 = a0 + 1024;
                float4 x0 = __ldcs((const float4*)(src + a0));
                float4 x1 = __ldcs((const float4*)(src + a1));

                float4 l0, u0, k0;
                l0.x = fmaf(alpha, x0.x, bl); u0.x = fmaf(alpha, x0.x, bu);
                l0.y = fmaf(alpha, x0.y, bl); u0.y = fmaf(alpha, x0.y, bu);
                l0.z = fmaf(alpha, x0.z, bl); u0.z = fmaf(alpha, x0.z, bu);
                l0.w = fmaf(alpha, x0.w, bl); u0.w = fmaf(alpha, x0.w, bu);
                k0.x = sigmoid_fast(u0.x) - sigmoid_fast(l0.x);
                k0.y = sigmoid_fast(u0.y) - sigmoid_fast(l0.y);
                k0.z = sigmoid_fast(u0.z) - sigmoid_fast(l0.z);
                k0.w = sigmoid_fast(u0.w) - sigmoid_fast(l0.w);
                __stcs((float4*)(lik + a0), k0);
                __stcs((float4*)(low + a0), l0);
                __stcs((float4*)(upp + a0), u0);

                float4 l1, u1, k1;
                l1.x = fmaf(alpha, x1.x, bl); u1.x = fmaf(alpha, x1.x, bu);
                l1.y = fmaf(alpha, x1.y, bl); u1.y = fmaf(alpha, x1.y, bu);
                l1.z = fmaf(alpha, x1.z, bl); u1.z = fmaf(alpha, x1.z, bu);
                l1.w = fmaf(alpha, x1.w, bl); u1.w = fmaf(alpha, x1.w, bu);
                k1.x = sigmoid_fast(u1.x) - sigmoid_fast(l1.x);
                k1.y = sigmoid_fast(u1.y) - sigmoid_fast(l1.y);
                k1.z = sigmoid_fast(u1.z) - sigmoid_fast(l1.z);
                k1.w = sigmoid_fast(u1.w) - sigmoid_fast(l1.w);
                __stcs((float4*)(lik + a1), k1);
                __stcs((float4*)(low + a1), l1);
                __stcs((float4*)(upp + a1), u1);
            }
        } else {
            for (int i = 0; i < 4; i++) {
                int s = blk + i * 1024 + tid * 4;
                int lim = min(s + 4, N);
                for (int q = s; q < lim; q++) {
                    float x = src[q];
                    float l = fmaf(alpha, x, bl);
                    float u = fmaf(alpha, x, bu);
                    lik[q] = sigmoid_fast(u) - sigmoid_fast(l);
                    low[q] = l;
                    upp[q] = u;
                }
            }
        }
    } else {
        // ---- COLD safety net: full MLP for this slice (never taken) --------
        const int end = min(blk + EPB, N);
        for (int e = blk + tid; e < end; e += 256) {
            float x = src[e];
            float r2[2];
            #pragma unroll
            for (int s = 0; s < 2; s++) {
                float xi = x + (s ? 0.5f : -0.5f);
                float y0 = fmaf(sP[0], xi, sP[3]);
                float y1 = fmaf(sP[1], xi, sP[4]);
                float y2 = fmaf(sP[2], xi, sP[5]);
                y0 = fmaf(sP[6], tanhf(y0), y0);
                y1 = fmaf(sP[7], tanhf(y1), y1);
                y2 = fmaf(sP[8], tanhf(y2), y2);
                #pragma unroll
                for (int l = 0; l < 3; l++) {
                    const float* W = sP + 9 + l * 15;
                    const float* B = W + 9;
                    const float* T = W + 12;
                    float z0 = W[0] * y0 + W[1] * y1 + W[2] * y2 + B[0];
                    float z1 = W[3] * y0 + W[4] * y1 + W[5] * y2 + B[1];
                    float z2 = W[6] * y0 + W[7] * y1 + W[8] * y2 + B[2];
                    y0 = fmaf(T[0], tanhf(z0), z0);
                    y1 = fmaf(T[1], tanhf(z1), z1);
                    y2 = fmaf(T[2], tanhf(z2), z2);
                }
                r2[s] = sP[54] * y0 + sP[55] * y1 + sP[56] * y2 + sP[57];
            }
            lik[e] = 1.0f / (1.0f + expf(-r2[1])) - 1.0f / (1.0f + expf(-r2[0]));
            low[e] = r2[0];
            upp[e] = r2[1];
        }
    }
}

// ---------------------------------------------------------------------------
// Host launcher — single kernel launch.
// ---------------------------------------------------------------------------
extern "C" void kernel_launch(void* const* d_in, const int* in_sizes, int n_in,
                              void* d_out, int out_size)
{
    // Input-order detection.
    // Order A (dict order): inputs, m0,b0,t0, m1,b1,t1, m2,b2,t2, m3,b3,t3, m4,b4
    // Order B (signature):  inputs, m0..m4, b0..b4, t0..t3
    int im[5], ib[5], it[4];
    if (n_in >= 15 && in_sizes[2] == in_sizes[1]) {
        im[0] = 1;  ib[0] = 2;  it[0] = 3;
        im[1] = 4;  ib[1] = 5;  it[1] = 6;
        im[2] = 7;  ib[2] = 8;  it[2] = 9;
        im[3] = 10; ib[3] = 11; it[3] = 12;
        im[4] = 13; ib[4] = 14;
    } else {
        im[0] = 1; im[1] = 2; im[2] = 3; im[3] = 4; im[4] = 5;
        ib[0] = 6; ib[1] = 7; ib[2] = 8; ib[3] = 9; ib[4] = 10;
        it[0] = 11; it[1] = 12; it[2] = 13; it[3] = 14;
    }

    const float* in = (const float*)d_in[0];
    float* out = (float*)d_out;

    int C = in_sizes[ib[4]];          // b4 is (C,1,1)
    if (C <= 0 || C > 256) C = 192;
    int N = in_sizes[0] / C;
    long long CN = (long long)C * N;

    dim3 grid((N + EPB - 1) / EPB, C);
    eb_kernel<<<grid, 256>>>(
        in, out,
        (const float*)d_in[im[0]], (const float*)d_in[ib[0]], (const float*)d_in[it[0]],
        (const float*)d_in[im[1]], (const float*)d_in[ib[1]], (const float*)d_in[it[1]],
        (const float*)d_in[im[2]], (const float*)d_in[ib[2]], (const float*)d_in[it[2]],
        (const float*)d_in[im[3]], (const float*)d_in[ib[3]], (const float*)d_in[it[3]],
        (const float*)d_in[im[4]], (const float*)d_in[ib[4]],
        N, CN);
}

// round 12
// speedup vs baseline: 1.0466x; 1.0056x over previous
#include <cuda_runtime.h>
#include <math.h>

// EntropyBottleneck — single kernel, barrier-free producer/consumer params.
//
// Structure exploited (verified at runtime per channel):
//   * every m{i} constant-filled -> rank-1 layers
//   * every t{i} == 0            -> tanh gating vanishes
// => lower = alpha*x + beta_l, upper = alpha*x + beta_u per channel.
//
// Block (0,c) produces channel c's params (parallel fold, publish, fence,
// flag). Consumer blocks spin on a coalesced ld.global.cg of the flag (no
// barriers, no shared in the hot path), read {alpha,beta_l,beta_u} from L2,
// and stream. flag==2 => full-MLP fallback (cold, never taken here).

__device__ float4 g_abv[256];      // {alpha, beta_l, beta_u, -}
__device__ int    g_flag[256];     // 0 = not ready, 1 = affine, 2 = fallback
__device__ float  g_pf[256][64];   // full transformed params (fallback only)

// Flat param layout: [0..2]W0 [3..5]B0 [6..8]T0
// layer l in {0,1,2}: base=9+l*15 -> W[0..8], B[9..11], T[12..14]
// [54..56]W4 [57]B4
#define NPARAM 58

__device__ __forceinline__ float softplus_f(float v) {
    if (v > 20.0f) return v;
    if (v < -20.0f) return expf(v);
    return log1pf(expf(v));
}

__device__ __forceinline__ float sigmoid_fast(float x) {
    float e = __expf(-x);
    return __fdividef(1.0f, 1.0f + e);
}

__device__ __forceinline__ int ldcg_i32(const int* p) {
    int v;
    asm volatile("ld.global.cg.b32 %0, [%1];" : "=r"(v) : "l"(p));
    return v;
}

__device__ __forceinline__ float4 ldcg_f4(const float4* p) {
    float4 v;
    asm volatile("ld.global.cg.v4.f32 {%0,%1,%2,%3}, [%4];"
                 : "=f"(v.x), "=f"(v.y), "=f"(v.z), "=f"(v.w) : "l"(p));
    return v;
}

#define EPB 4096   // 256 threads * 4 float4

__global__ __launch_bounds__(256, 6) void eb_kernel(
    const float* __restrict__ in, float* __restrict__ out,
    const float* __restrict__ m0, const float* __restrict__ b0, const float* __restrict__ t0,
    const float* __restrict__ m1, const float* __restrict__ b1, const float* __restrict__ t1,
    const float* __restrict__ m2, const float* __restrict__ b2, const float* __restrict__ t2,
    const float* __restrict__ m3, const float* __restrict__ b3, const float* __restrict__ t3,
    const float* __restrict__ m4, const float* __restrict__ b4,
    int N, long long CN)
{
    const int c   = blockIdx.y;
    const int tid = threadIdx.x;

    const long long base = (long long)c * N;
    const int blk = blockIdx.x * EPB;
    const float* src = in + base;

    __shared__ float sP[NPARAM];
    __shared__ float sAbv[3];
    __shared__ int   sState;

    int   state;
    float alpha, bl, bu;

    if (blockIdx.x == 0) {
        // ================= PRODUCER (one block per channel) =================
        int ok = 1;
        if (tid < 3) {
            float v = __ldg(&m0[c * 3 + tid]);
            if (v != __ldg(&m0[c * 3])) ok = 0;
            sP[0 + tid] = softplus_f(v);
            sP[3 + tid] = __ldg(&b0[c * 3 + tid]);
            float tv = __ldg(&t0[c * 3 + tid]);
            if (tv != 0.0f) ok = 0;
            sP[6 + tid] = tanhf(tv);
        } else if (tid < 30) {
            int l = (tid - 3) / 9, j = (tid - 3) % 9;
            const float* m = (l == 0) ? m1 : (l == 1) ? m2 : m3;
            float v = __ldg(&m[c * 9 + j]);
            if (v != __ldg(&m[c * 9])) ok = 0;
            sP[9 + l * 15 + j] = softplus_f(v);
        } else if (tid < 33) {
            int j = tid - 30;
            float v = __ldg(&m4[c * 3 + j]);
            if (v != __ldg(&m4[c * 3])) ok = 0;
            sP[54 + j] = softplus_f(v);
        } else if (tid < 42) {
            int l = (tid - 33) / 3, j = (tid - 33) % 3;
            const float* b = (l == 0) ? b1 : (l == 1) ? b2 : b3;
            const float* t = (l == 0) ? t1 : (l == 1) ? t2 : t3;
            sP[9 + l * 15 + 9 + j] = __ldg(&b[c * 3 + j]);
            float tv = __ldg(&t[c * 3 + j]);
            if (tv != 0.0f) ok = 0;
            sP[9 + l * 15 + 12 + j] = tanhf(tv);
        } else if (tid == 42) {
            sP[57] = __ldg(&b4[c]);
        }
        const int flag = __syncthreads_and(ok);

        if (!flag && tid < NPARAM) g_pf[c][tid] = sP[tid];   // fallback params

        if (tid == 0) {
            float a = sP[0];
            a *= (sP[9]  + sP[10] + sP[11]);
            a *= (sP[24] + sP[25] + sP[26]);
            a *= (sP[39] + sP[40] + sP[41]);
            a *= (sP[54] + sP[55] + sP[56]);

            float y0 = sP[3], y1 = sP[4], y2 = sP[5];
            #pragma unroll
            for (int l = 0; l < 3; l++) {
                const float* W = sP + 9 + l * 15;
                const float* B = W + 9;
                float z0 = W[0] * y0 + W[1] * y1 + W[2] * y2 + B[0];
                float z1 = W[3] * y0 + W[4] * y1 + W[5] * y2 + B[1];
                float z2 = W[6] * y0 + W[7] * y1 + W[8] * y2 + B[2];
                y0 = z0; y1 = z1; y2 = z2;
            }
            float beta = sP[54] * y0 + sP[55] * y1 + sP[56] * y2 + sP[57];
            float hb = 0.5f * a;
            sAbv[0] = a; sAbv[1] = beta - hb; sAbv[2] = beta + hb;
            sState = flag ? 1 : 2;
            g_abv[c] = make_float4(a, beta - hb, beta + hb, 0.0f);
            __threadfence();                          // publish before flag
            atomicExch(&g_flag[c], flag ? 1 : 2);     // release
        }
        __syncthreads();
        state = sState;
        alpha = sAbv[0]; bl = sAbv[1]; bu = sAbv[2];
    } else {
        // ========== CONSUMER: barrier-free coalesced flag spin ==============
        int f = ldcg_i32(&g_flag[c]);
        while (f == 0) { __nanosleep(64); f = ldcg_i32(&g_flag[c]); }
        state = f;                                    // monotone 0->{1,2}
        float4 v = ldcg_f4(&g_abv[c]);                // L2 is coherence point
        alpha = v.x; bl = v.y; bu = v.z;
    }

    float* lik = out + base;
    float* low = out + CN + base;
    float* upp = out + 2 * CN + base;

    if (state == 1) {
        // ---- HOT stream: 4 float4/thread, paired-load ILP ------------------
        if (blk + EPB <= N) {             // block-uniform interior predicate
            #pragma unroll
            for (int i = 0; i < 2; i++) {
                const int a0 = blk + i * 2048 + tid * 4;
                const int a1 = a0 + 1024;
                float4 x0 = __ldcs((const float4*)(src + a0));
                float4 x1 = __ldcs((const float4*)(src + a1));

                float4 l0, u0, k0;
                l0.x = fmaf(alpha, x0.x, bl); u0.x = fmaf(alpha, x0.x, bu);
                l0.y = fmaf(alpha, x0.y, bl); u0.y = fmaf(alpha, x0.y, bu);
                l0.z = fmaf(alpha, x0.z, bl); u0.z = fmaf(alpha, x0.z, bu);
                l0.w = fmaf(alpha, x0.w, bl); u0.w = fmaf(alpha, x0.w, bu);
                k0.x = sigmoid_fast(u0.x) - sigmoid_fast(l0.x);
                k0.y = sigmoid_fast(u0.y) - sigmoid_fast(l0.y);
                k0.z = sigmoid_fast(u0.z) - sigmoid_fast(l0.z);
                k0.w = sigmoid_fast(u0.w) - sigmoid_fast(l0.w);
                __stcs((float4*)(lik + a0), k0);
                __stcs((float4*)(low + a0), l0);
                __stcs((float4*)(upp + a0), u0);

                float4 l1, u1, k1;
                l1.x = fmaf(alpha, x1.x, bl); u1.x = fmaf(alpha, x1.x, bu);
                l1.y = fmaf(alpha, x1.y, bl); u1.y = fmaf(alpha, x1.y, bu);
                l1.z = fmaf(alpha, x1.z, bl); u1.z = fmaf(alpha, x1.z, bu);
                l1.w = fmaf(alpha, x1.w, bl); u1.w = fmaf(alpha, x1.w, bu);
                k1.x = sigmoid_fast(u1.x) - sigmoid_fast(l1.x);
                k1.y = sigmoid_fast(u1.y) - sigmoid_fast(l1.y);
                k1.z = sigmoid_fast(u1.z) - sigmoid_fast(l1.z);
                k1.w = sigmoid_fast(u1.w) - sigmoid_fast(l1.w);
                __stcs((float4*)(lik + a1), k1);
                __stcs((float4*)(low + a1), l1);
                __stcs((float4*)(upp + a1), u1);
            }
        } else {
            for (int i = 0; i < 4; i++) {
                int s = blk + i * 1024 + tid * 4;
                int lim = min(s + 4, N);
                for (int q = s; q < lim; q++) {
                    float x = src[q];
                    float l = fmaf(alpha, x, bl);
                    float u = fmaf(alpha, x, bu);
                    lik[q] = sigmoid_fast(u) - sigmoid_fast(l);
                    low[q] = l;
                    upp[q] = u;
                }
            }
        }
    } else {
        // ---- COLD safety net: full MLP for this slice (never taken) --------
        if (blockIdx.x != 0) {            // consumers fetch published params
            if (tid < NPARAM) sP[tid] = __ldcg(&g_pf[c][tid]);
            __syncthreads();
        }
        const int end = min(blk + EPB, N);
        for (int e = blk + tid; e < end; e += 256) {
            float x = src[e];
            float r2[2];
            #pragma unroll
            for (int s = 0; s < 2; s++) {
                float xi = x + (s ? 0.5f : -0.5f);
                float y0 = fmaf(sP[0], xi, sP[3]);
                float y1 = fmaf(sP[1], xi, sP[4]);
                float y2 = fmaf(sP[2], xi, sP[5]);
                y0 = fmaf(sP[6], tanhf(y0), y0);
                y1 = fmaf(sP[7], tanhf(y1), y1);
                y2 = fmaf(sP[8], tanhf(y2), y2);
                #pragma unroll
                for (int l = 0; l < 3; l++) {
                    const float* W = sP + 9 + l * 15;
                    const float* B = W + 9;
                    const float* T = W + 12;
                    float z0 = W[0] * y0 + W[1] * y1 + W[2] * y2 + B[0];
                    float z1 = W[3] * y0 + W[4] * y1 + W[5] * y2 + B[1];
                    float z2 = W[6] * y0 + W[7] * y1 + W[8] * y2 + B[2];
                    y0 = fmaf(T[0], tanhf(z0), z0);
                    y1 = fmaf(T[1], tanhf(z1), z1);
                    y2 = fmaf(T[2], tanhf(z2), z2);
                }
                r2[s] = sP[54] * y0 + sP[55] * y1 + sP[56] * y2 + sP[57];
            }
            lik[e] = 1.0f / (1.0f + expf(-r2[1])) - 1.0f / (1.0f + expf(-r2[0]));
            low[e] = r2[0];
            upp[e] = r2[1];
        }
    }
}

// ---------------------------------------------------------------------------
// Host launcher — single kernel launch.
// ---------------------------------------------------------------------------
extern "C" void kernel_launch(void* const* d_in, const int* in_sizes, int n_in,
                              void* d_out, int out_size)
{
    // Input-order detection.
    // Order A (dict order): inputs, m0,b0,t0, m1,b1,t1, m2,b2,t2, m3,b3,t3, m4,b4
    // Order B (signature):  inputs, m0..m4, b0..b4, t0..t3
    int im[5], ib[5], it[4];
    if (n_in >= 15 && in_sizes[2] == in_sizes[1]) {
        im[0] = 1;  ib[0] = 2;  it[0] = 3;
        im[1] = 4;  ib[1] = 5;  it[1] = 6;
        im[2] = 7;  ib[2] = 8;  it[2] = 9;
        im[3] = 10; ib[3] = 11; it[3] = 12;
        im[4] = 13; ib[4] = 14;
    } else {
        im[0] = 1; im[1] = 2; im[2] = 3; im[3] = 4; im[4] = 5;
        ib[0] = 6; ib[1] = 7; ib[2] = 8; ib[3] = 9; ib[4] = 10;
        it[0] = 11; it[1] = 12; it[2] = 13; it[3] = 14;
    }

    const float* in = (const float*)d_in[0];
    float* out = (float*)d_out;

    int C = in_sizes[ib[4]];          // b4 is (C,1,1)
    if (C <= 0 || C > 256) C = 192;
    int N = in_sizes[0] / C;
    long long CN = (long long)C * N;

    dim3 grid((N + EPB - 1) / EPB, C);
    eb_kernel<<<grid, 256>>>(
        in, out,
        (const float*)d_in[im[0]], (const float*)d_in[ib[0]], (const float*)d_in[it[0]],
        (const float*)d_in[im[1]], (const float*)d_in[ib[1]], (const float*)d_in[it[1]],
        (const float*)d_in[im[2]], (const float*)d_in[ib[2]], (const float*)d_in[it[2]],
        (const float*)d_in[im[3]], (const float*)d_in[ib[3]], (const float*)d_in[it[3]],
        (const float*)d_in[im[4]], (const float*)d_in[ib[4]],
        N, CN);
}

// round 14
// speedup vs baseline: 1.0613x; 1.0140x over previous
#include <cuda_runtime.h>
#include <math.h>

// EntropyBottleneck — single kernel, single-word producer/consumer handshake.
//
// Structure exploited (verified at runtime per channel):
//   * every m{i} constant-filled -> rank-1 layers
//   * every t{i} == 0            -> tanh gating vanishes
// => lower = alpha*x + beta_l, upper = alpha*x + beta_u per channel.
//
// Block (0,c) produces channel c's params and publishes {alpha, beta_l,
// beta_u, state} in ONE 16B cg-store. Consumers issue their first input
// loads FIRST, then spin on one 16B cg-load (w==0 => not ready) — the
// handshake L2 trip hides under the input DRAM trip. state==2 => full-MLP
// fallback from g_pf (cold, never taken on this problem's inputs).

__device__ float4 g_abv[256];      // {alpha, beta_l, beta_u, state}
__device__ float  g_pf[256][64];   // full transformed params (fallback only)

// Flat param layout: [0..2]W0 [3..5]B0 [6..8]T0
// layer l in {0,1,2}: base=9+l*15 -> W[0..8], B[9..11], T[12..14]
// [54..56]W4 [57]B4
#define NPARAM 58

__device__ __forceinline__ float softplus_f(float v) {
    if (v > 20.0f) return v;
    if (v < -20.0f) return expf(v);
    return log1pf(expf(v));
}

__device__ __forceinline__ float sigmoid_fast(float x) {
    float e = __expf(-x);
    return __fdividef(1.0f, 1.0f + e);
}

__device__ __forceinline__ float4 ldcg_f4(const float4* p) {
    float4 v;
    asm volatile("ld.global.cg.v4.f32 {%0,%1,%2,%3}, [%4];"
                 : "=f"(v.x), "=f"(v.y), "=f"(v.z), "=f"(v.w) : "l"(p));
    return v;
}

__device__ __forceinline__ void stcg_f4(float4* p, float4 v) {
    asm volatile("st.global.cg.v4.f32 [%0], {%1,%2,%3,%4};"
                 :: "l"(p), "f"(v.x), "f"(v.y), "f"(v.z), "f"(v.w) : "memory");
}

#define EPB 4096   // 256 threads * 4 float4

__global__ __launch_bounds__(256, 6) void eb_kernel(
    const float* __restrict__ in, float* __restrict__ out,
    const float* __restrict__ m0, const float* __restrict__ b0, const float* __restrict__ t0,
    const float* __restrict__ m1, const float* __restrict__ b1, const float* __restrict__ t1,
    const float* __restrict__ m2, const float* __restrict__ b2, const float* __restrict__ t2,
    const float* __restrict__ m3, const float* __restrict__ b3, const float* __restrict__ t3,
    const float* __restrict__ m4, const float* __restrict__ b4,
    int N, long long CN)
{
    const int c   = blockIdx.y;
    const int tid = threadIdx.x;

    const long long base = (long long)c * N;
    const int blk = blockIdx.x * EPB;
    const float* src = in + base;
    const bool interior = (blk + EPB <= N);

    __shared__ float sP[NPARAM];
    __shared__ float sAbv[4];

    float alpha, bl, bu, statef;
    float4 x0, x1;                       // first pair, preloaded pre-handshake

    if (blockIdx.x == 0) {
        // ================= PRODUCER (one block per channel) =================
        int ok = 1;
        if (tid < 3) {
            float v = __ldg(&m0[c * 3 + tid]);
            if (v != __ldg(&m0[c * 3])) ok = 0;
            sP[0 + tid] = softplus_f(v);
            sP[3 + tid] = __ldg(&b0[c * 3 + tid]);
            float tv = __ldg(&t0[c * 3 + tid]);
            if (tv != 0.0f) ok = 0;
            sP[6 + tid] = tanhf(tv);
        } else if (tid < 30) {
            int l = (tid - 3) / 9, j = (tid - 3) % 9;
            const float* m = (l == 0) ? m1 : (l == 1) ? m2 : m3;
            float v = __ldg(&m[c * 9 + j]);
            if (v != __ldg(&m[c * 9])) ok = 0;
            sP[9 + l * 15 + j] = softplus_f(v);
        } else if (tid < 33) {
            int j = tid - 30;
            float v = __ldg(&m4[c * 3 + j]);
            if (v != __ldg(&m4[c * 3])) ok = 0;
            sP[54 + j] = softplus_f(v);
        } else if (tid < 42) {
            int l = (tid - 33) / 3, j = (tid - 33) % 3;
            const float* b = (l == 0) ? b1 : (l == 1) ? b2 : b3;
            const float* t = (l == 0) ? t1 : (l == 1) ? t2 : t3;
            sP[9 + l * 15 + 9 + j] = __ldg(&b[c * 3 + j]);
            float tv = __ldg(&t[c * 3 + j]);
            if (tv != 0.0f) ok = 0;
            sP[9 + l * 15 + 12 + j] = tanhf(tv);
        } else if (tid == 42) {
            sP[57] = __ldg(&b4[c]);
        }
        const int flag = __syncthreads_and(ok);

        if (!flag && tid < NPARAM) g_pf[c][tid] = sP[tid];   // fallback params
        if (!flag) { __syncthreads(); if (tid == 0) __threadfence(); }

        if (tid == 0) {
            float a = sP[0];
            a *= (sP[9]  + sP[10] + sP[11]);
            a *= (sP[24] + sP[25] + sP[26]);
            a *= (sP[39] + sP[40] + sP[41]);
            a *= (sP[54] + sP[55] + sP[56]);

            float y0 = sP[3], y1 = sP[4], y2 = sP[5];
            #pragma unroll
            for (int l = 0; l < 3; l++) {
                const float* W = sP + 9 + l * 15;
                const float* B = W + 9;
                float z0 = W[0] * y0 + W[1] * y1 + W[2] * y2 + B[0];
                float z1 = W[3] * y0 + W[4] * y1 + W[5] * y2 + B[1];
                float z2 = W[6] * y0 + W[7] * y1 + W[8] * y2 + B[2];
                y0 = z0; y1 = z1; y2 = z2;
            }
            float beta = sP[54] * y0 + sP[55] * y1 + sP[56] * y2 + sP[57];
            float hb = 0.5f * a;
            float st = flag ? 1.0f : 2.0f;
            sAbv[0] = a; sAbv[1] = beta - hb; sAbv[2] = beta + hb; sAbv[3] = st;
            // single-16B-store publication: payload + flag in one sector
            stcg_f4(&g_abv[c], make_float4(a, beta - hb, beta + hb, st));
        }
        __syncthreads();
        alpha = sAbv[0]; bl = sAbv[1]; bu = sAbv[2]; statef = sAbv[3];
        if (interior) {
            x0 = __ldcs((const float4*)(src + blk + tid * 4));
            x1 = __ldcs((const float4*)(src + blk + tid * 4 + 1024));
        }
    } else {
        // ===== CONSUMER: input loads FIRST, then one-word handshake =========
        if (interior) {
            x0 = __ldcs((const float4*)(src + blk + tid * 4));
            x1 = __ldcs((const float4*)(src + blk + tid * 4 + 1024));
        }
        float4 v = ldcg_f4(&g_abv[c]);
        while (v.w == 0.0f) { __nanosleep(64); v = ldcg_f4(&g_abv[c]); }
        alpha = v.x; bl = v.y; bu = v.z; statef = v.w;
    }

    float* lik = out + base;
    float* low = out + CN + base;
    float* upp = out + 2 * CN + base;

    if (statef == 1.0f) {
        // ---- HOT stream: 4 float4/thread, paired-load ILP ------------------
        if (interior) {
            #pragma unroll
            for (int i = 0; i < 2; i++) {
                const int a0 = blk + i * 2048 + tid * 4;
                const int a1 = a0 + 1024;
                if (i) {                  // second pair loaded in-loop
                    x0 = __ldcs((const float4*)(src + a0));
                    x1 = __ldcs((const float4*)(src + a1));
                }

                float4 l0, u0, k0;
                l0.x = fmaf(alpha, x0.x, bl); u0.x = fmaf(alpha, x0.x, bu);
                l0.y = fmaf(alpha, x0.y, bl); u0.y = fmaf(alpha, x0.y, bu);
                l0.z = fmaf(alpha, x0.z, bl); u0.z = fmaf(alpha, x0.z, bu);
                l0.w = fmaf(alpha, x0.w, bl); u0.w = fmaf(alpha, x0.w, bu);
                k0.x = sigmoid_fast(u0.x) - sigmoid_fast(l0.x);
                k0.y = sigmoid_fast(u0.y) - sigmoid_fast(l0.y);
                k0.z = sigmoid_fast(u0.z) - sigmoid_fast(l0.z);
                k0.w = sigmoid_fast(u0.w) - sigmoid_fast(l0.w);
                __stcs((float4*)(lik + a0), k0);
                __stcs((float4*)(low + a0), l0);
                __stcs((float4*)(upp + a0), u0);

                float4 l1, u1, k1;
                l1.x = fmaf(alpha, x1.x, bl); u1.x = fmaf(alpha, x1.x, bu);
                l1.y = fmaf(alpha, x1.y, bl); u1.y = fmaf(alpha, x1.y, bu);
                l1.z = fmaf(alpha, x1.z, bl); u1.z = fmaf(alpha, x1.z, bu);
                l1.w = fmaf(alpha, x1.w, bl); u1.w = fmaf(alpha, x1.w, bu);
                k1.x = sigmoid_fast(u1.x) - sigmoid_fast(l1.x);
                k1.y = sigmoid_fast(u1.y) - sigmoid_fast(l1.y);
                k1.z = sigmoid_fast(u1.z) - sigmoid_fast(l1.z);
                k1.w = sigmoid_fast(u1.w) - sigmoid_fast(l1.w);
                __stcs((float4*)(lik + a1), k1);
                __stcs((float4*)(low + a1), l1);
                __stcs((float4*)(upp + a1), u1);
            }
        } else {
            for (int i = 0; i < 4; i++) {
                int s = blk + i * 1024 + tid * 4;
                int lim = min(s + 4, N);
                for (int q = s; q < lim; q++) {
                    float x = src[q];
                    float l = fmaf(alpha, x, bl);
                    float u = fmaf(alpha, x, bu);
                    lik[q] = sigmoid_fast(u) - sigmoid_fast(l);
                    low[q] = l;
                    upp[q] = u;
                }
            }
        }
    } else {
        // ---- COLD safety net: full MLP for this slice (never taken) --------
        if (blockIdx.x != 0) {            // consumers fetch published params
            if (tid < NPARAM) sP[tid] = __ldcg(&g_pf[c][tid]);
            __syncthreads();
        }
        const int end = min(blk + EPB, N);
        for (int e = blk + tid; e < end; e += 256) {
            float x = src[e];
            float r2[2];
            #pragma unroll
            for (int s = 0; s < 2; s++) {
                float xi = x + (s ? 0.5f : -0.5f);
                float y0 = fmaf(sP[0], xi, sP[3]);
                float y1 = fmaf(sP[1], xi, sP[4]);
                float y2 = fmaf(sP[2], xi, sP[5]);
                y0 = fmaf(sP[6], tanhf(y0), y0);
                y1 = fmaf(sP[7], tanhf(y1), y1);
                y2 = fmaf(sP[8], tanhf(y2), y2);
                #pragma unroll
                for (int l = 0; l < 3; l++) {
                    const float* W = sP + 9 + l * 15;
                    const float* B = W + 9;
                    const float* T = W + 12;
                    float z0 = W[0] * y0 + W[1] * y1 + W[2] * y2 + B[0];
                    float z1 = W[3] * y0 + W[4] * y1 + W[5] * y2 + B[1];
                    float z2 = W[6] * y0 + W[7] * y1 + W[8] * y2 + B[2];
                    y0 = fmaf(T[0], tanhf(z0), z0);
                    y1 = fmaf(T[1], tanhf(z1), z1);
                    y2 = fmaf(T[2], tanhf(z2), z2);
                }
                r2[s] = sP[54] * y0 + sP[55] * y1 + sP[56] * y2 + sP[57];
            }
            lik[e] = 1.0f / (1.0f + expf(-r2[1])) - 1.0f / (1.0f + expf(-r2[0]));
            low[e] = r2[0];
            upp[e] = r2[1];
        }
    }
}

// ---------------------------------------------------------------------------
// Host launcher — single kernel launch.
// ---------------------------------------------------------------------------
extern "C" void kernel_launch(void* const* d_in, const int* in_sizes, int n_in,
                              void* d_out, int out_size)
{
    // Input-order detection.
    // Order A (dict order): inputs, m0,b0,t0, m1,b1,t1, m2,b2,t2, m3,b3,t3, m4,b4
    // Order B (signature):  inputs, m0..m4, b0..b4, t0..t3
    int im[5], ib[5], it[4];
    if (n_in >= 15 && in_sizes[2] == in_sizes[1]) {
        im[0] = 1;  ib[0] = 2;  it[0] = 3;
        im[1] = 4;  ib[1] = 5;  it[1] = 6;
        im[2] = 7;  ib[2] = 8;  it[2] = 9;
        im[3] = 10; ib[3] = 11; it[3] = 12;
        im[4] = 13; ib[4] = 14;
    } else {
        im[0] = 1; im[1] = 2; im[2] = 3; im[3] = 4; im[4] = 5;
        ib[0] = 6; ib[1] = 7; ib[2] = 8; ib[3] = 9; ib[4] = 10;
        it[0] = 11; it[1] = 12; it[2] = 13; it[3] = 14;
    }

    const float* in = (const float*)d_in[0];
    float* out = (float*)d_out;

    int C = in_sizes[ib[4]];          // b4 is (C,1,1)
    if (C <= 0 || C > 256) C = 192;
    int N = in_sizes[0] / C;
    long long CN = (long long)C * N;

    dim3 grid((N + EPB - 1) / EPB, C);
    eb_kernel<<<grid, 256>>>(
        in, out,
        (const float*)d_in[im[0]], (const float*)d_in[ib[0]], (const float*)d_in[it[0]],
        (const float*)d_in[im[1]], (const float*)d_in[ib[1]], (const float*)d_in[it[1]],
        (const float*)d_in[im[2]], (const float*)d_in[ib[2]], (const float*)d_in[it[2]],
        (const float*)d_in[im[3]], (const float*)d_in[ib[3]], (const float*)d_in[it[3]],
        (const float*)d_in[im[4]], (const float*)d_in[ib[4]],
        N, CN);
}